// round 1
// baseline (speedup 1.0000x reference)
#include <cuda_runtime.h>

// Problem constants
constexpr int BATCH = 128;
constexpr int TSEQ  = 512;
constexpr int KIN   = 906;   // input feature dim
constexpr int HID   = 4;
constexpr int NG    = 16;    // 4*H gates

// Scratch (device globals; no allocation allowed)
__device__ __align__(16) float g_xp[BATCH * TSEQ * NG];  // permuted [b][t][j][p], p in {i,f,g,o}
__device__ float g_hf[BATCH * HID];

// ---------- packed fp32x2 helpers (Blackwell FFMA2) ----------
__device__ __forceinline__ unsigned long long pack2(float x) {
    unsigned long long r;
    asm("mov.b64 %0, {%1, %1};" : "=l"(r) : "f"(x));
    return r;
}
__device__ __forceinline__ unsigned long long fma2(unsigned long long a,
                                                   unsigned long long b,
                                                   unsigned long long c) {
    unsigned long long d;
    asm("fma.rn.f32x2 %0, %1, %2, %3;" : "=l"(d) : "l"(a), "l"(b), "l"(c));
    return d;
}
__device__ __forceinline__ void unpack2(unsigned long long a, float& lo, float& hi) {
    asm("mov.b64 {%0, %1}, %2;" : "=f"(lo), "=f"(hi) : "l"(a));
}

// ---------- fast-but-accurate activations (EX2+RCP, ~1e-7 rel err) ----------
__device__ __forceinline__ float sigmoidf_(float x) {
    float e = __expf(-x);                    // FMUL + MUFU.EX2
    return __fdividef(1.0f, 1.0f + e);       // MUFU.RCP + FMUL
}
__device__ __forceinline__ float tanhf_(float x) {
    float e = __expf(2.0f * x);              // inf for large x is fine
    return 1.0f - __fdividef(2.0f, 1.0f + e);
}

// =====================================================================
// Kernel 1: projection  xp = x @ W_ih_f^T + (b_ih_f + b_hh_f)
// Block = 128 threads = 128 rows (row = b*T + t). 29 k-chunks of 32.
// Register-prefetch double buffering; SMEM x tile pad-33 (conflict-free);
// W chunk broadcast via LDS.128; accumulation in fp32x2 pairs.
// =====================================================================
__global__ __launch_bounds__(128) void proj_kernel(const float* __restrict__ x,
                                                   const float* __restrict__ Wih,
                                                   const float* __restrict__ bih,
                                                   const float* __restrict__ bhh) {
    __shared__ float sx[128 * 33];                     // [row][k] pad 33
    __shared__ __align__(16) float sw[32 * 16];        // [k][gate]

    const int tid = threadIdx.x;
    const int wid = tid >> 5;
    const int ln  = tid & 31;
    const size_t row0 = (size_t)blockIdx.x * 128;

    unsigned long long acc[8];
#pragma unroll
    for (int m = 0; m < 8; ++m) acc[m] = 0ull;

    float xreg[32];
    float wreg[4];

    constexpr int NCH = (KIN + 31) / 32;  // 29

    // ---- prefetch chunk into registers (coalesced LDG) ----
    auto ldg_chunk = [&](int kc) {
        const int k = kc + ln;
        const bool ok = (k < KIN);
#pragma unroll
        for (int i = 0; i < 32; ++i) {
            const int r = wid + 4 * i;
            xreg[i] = ok ? __ldg(&x[(row0 + r) * KIN + k]) : 0.0f;
        }
#pragma unroll
        for (int jj = 0; jj < 4; ++jj) {
            const int g = wid + 4 * jj;
            wreg[jj] = ok ? __ldg(&Wih[(size_t)g * KIN + k]) : 0.0f;
        }
    };
    auto sts_chunk = [&]() {
#pragma unroll
        for (int i = 0; i < 32; ++i) sx[(wid + 4 * i) * 33 + ln] = xreg[i];
#pragma unroll
        for (int jj = 0; jj < 4; ++jj) sw[ln * 16 + (wid + 4 * jj)] = wreg[jj];
    };

#define PROJ_BODY(KK)                                                         \
    {                                                                         \
        const float xk = sx[tid * 33 + (KK)];                                 \
        const unsigned long long xx = pack2(xk);                              \
        const ulonglong2* wr = (const ulonglong2*)(sw + (KK) * 16);           \
        ulonglong2 wa = wr[0], wb = wr[1];                                    \
        acc[0] = fma2(xx, wa.x, acc[0]);                                      \
        acc[1] = fma2(xx, wa.y, acc[1]);                                      \
        acc[2] = fma2(xx, wb.x, acc[2]);                                      \
        acc[3] = fma2(xx, wb.y, acc[3]);                                      \
        ulonglong2 wc = wr[2], wd = wr[3];                                    \
        acc[4] = fma2(xx, wc.x, acc[4]);                                      \
        acc[5] = fma2(xx, wc.y, acc[5]);                                      \
        acc[6] = fma2(xx, wd.x, acc[6]);                                      \
        acc[7] = fma2(xx, wd.y, acc[7]);                                      \
    }

    ldg_chunk(0);
    sts_chunk();
    __syncthreads();

    for (int ch = 0; ch < NCH; ++ch) {
        const int kc = ch * 32;
        if (ch + 1 < NCH) ldg_chunk(kc + 32);  // issue next-chunk loads early

        const int kcn = (KIN - kc < 32) ? (KIN - kc) : 32;
        if (kcn == 32) {
#pragma unroll
            for (int kk = 0; kk < 32; ++kk) PROJ_BODY(kk);
        } else {
            for (int kk = 0; kk < kcn; ++kk) PROJ_BODY(kk);
        }
        __syncthreads();
        if (ch + 1 < NCH) {
            sts_chunk();
            __syncthreads();
        }
    }
#undef PROJ_BODY

    // ---- epilogue: unpack, add bias, permuted store [j][p] ----
    float v[16];
#pragma unroll
    for (int m = 0; m < 8; ++m) unpack2(acc[m], v[2 * m], v[2 * m + 1]);
#pragma unroll
    for (int g = 0; g < 16; ++g) v[g] += __ldg(&bih[g]) + __ldg(&bhh[g]);

    const size_t base = (row0 + tid) * NG;
#pragma unroll
    for (int j = 0; j < 4; ++j) {
        float4 o4 = make_float4(v[j], v[4 + j], v[8 + j], v[12 + j]);
        *reinterpret_cast<float4*>(&g_xp[base + j * 4]) = o4;
    }
}

// =====================================================================
// Kernel 2: forward LSTM recurrence. 16 blocks x 32 threads.
// 4 lanes per batch; lane j owns h_j; h replicated via width-4 shuffles.
// =====================================================================
__global__ __launch_bounds__(32) void lstm_fwd_kernel(const float* __restrict__ Whh) {
    const int lane = threadIdx.x;
    const int j = lane & 3;
    const int bi = blockIdx.x * 8 + (lane >> 2);

    // W_hh rows for this lane's gate outputs: i=row j, f=row 4+j, g=row 8+j, o=row 12+j
    float wi[4], wf[4], wg[4], wo[4];
#pragma unroll
    for (int k = 0; k < 4; ++k) {
        wi[k] = __ldg(&Whh[(0 + j) * 4 + k]);
        wf[k] = __ldg(&Whh[(4 + j) * 4 + k]);
        wg[k] = __ldg(&Whh[(8 + j) * 4 + k]);
        wo[k] = __ldg(&Whh[(12 + j) * 4 + k]);
    }

    float h0 = 0.f, h1 = 0.f, h2 = 0.f, h3 = 0.f, c = 0.f, hj = 0.f;

    const float4* xp = reinterpret_cast<const float4*>(g_xp) + (size_t)bi * TSEQ * 4 + j;
    float4 pre = xp[0];

#pragma unroll 4
    for (int t = 0; t < TSEQ; ++t) {
        float4 nxt = (t + 1 < TSEQ) ? xp[(size_t)(t + 1) * 4] : pre;

        float ip = fmaf(wi[3], h3, fmaf(wi[2], h2, fmaf(wi[1], h1, fmaf(wi[0], h0, pre.x))));
        float fp = fmaf(wf[3], h3, fmaf(wf[2], h2, fmaf(wf[1], h1, fmaf(wf[0], h0, pre.y))));
        float gp = fmaf(wg[3], h3, fmaf(wg[2], h2, fmaf(wg[1], h1, fmaf(wg[0], h0, pre.z))));
        float op = fmaf(wo[3], h3, fmaf(wo[2], h2, fmaf(wo[1], h1, fmaf(wo[0], h0, pre.w))));

        float iv = sigmoidf_(ip);
        float fv = sigmoidf_(fp);
        float gv = tanhf_(gp);
        float ov = sigmoidf_(op);

        c  = fmaf(fv, c, iv * gv);
        hj = ov * tanhf_(c);

        h0 = __shfl_sync(0xffffffffu, hj, 0, 4);
        h1 = __shfl_sync(0xffffffffu, hj, 1, 4);
        h2 = __shfl_sync(0xffffffffu, hj, 2, 4);
        h3 = __shfl_sync(0xffffffffu, hj, 3, 4);

        pre = nxt;
    }

    g_hf[bi * HID + j] = hj;
}

// =====================================================================
// Kernel 3: backward direction collapses to ONE cell on x[:,T-1]
// (h0=c0=0 => W_hh_b unused, f-gate unused), plus the output head.
// Block per batch; warp w computes gates 4w..4w+3 by K-split + reduce.
// =====================================================================
__global__ __launch_bounds__(128) void tail_kernel(const float* __restrict__ x,
                                                   const float* __restrict__ Wihb,
                                                   const float* __restrict__ bihb,
                                                   const float* __restrict__ bhhb,
                                                   const float* __restrict__ Wout,
                                                   const float* __restrict__ bout,
                                                   float* __restrict__ out) {
    const int b = blockIdx.x;
    const int tid = threadIdx.x;
    const int w = tid >> 5;
    const int l = tid & 31;

    __shared__ float sg[16];

    const float* xr = x + ((size_t)b * TSEQ + (TSEQ - 1)) * KIN;

    float a0 = 0.f, a1 = 0.f, a2 = 0.f, a3 = 0.f;
    for (int k = l; k < KIN; k += 32) {
        float xv = __ldg(&xr[k]);
        a0 = fmaf(xv, __ldg(&Wihb[(size_t)(4 * w + 0) * KIN + k]), a0);
        a1 = fmaf(xv, __ldg(&Wihb[(size_t)(4 * w + 1) * KIN + k]), a1);
        a2 = fmaf(xv, __ldg(&Wihb[(size_t)(4 * w + 2) * KIN + k]), a2);
        a3 = fmaf(xv, __ldg(&Wihb[(size_t)(4 * w + 3) * KIN + k]), a3);
    }
#pragma unroll
    for (int s = 16; s > 0; s >>= 1) {
        a0 += __shfl_xor_sync(0xffffffffu, a0, s);
        a1 += __shfl_xor_sync(0xffffffffu, a1, s);
        a2 += __shfl_xor_sync(0xffffffffu, a2, s);
        a3 += __shfl_xor_sync(0xffffffffu, a3, s);
    }
    if (l == 0) {
        sg[4 * w + 0] = a0;
        sg[4 * w + 1] = a1;
        sg[4 * w + 2] = a2;
        sg[4 * w + 3] = a3;
    }
    __syncthreads();

    if (tid == 0) {
        float hb[4], hf[4];
#pragma unroll
        for (int jj = 0; jj < 4; ++jj) {
            float ip = sg[jj]      + __ldg(&bihb[jj])      + __ldg(&bhhb[jj]);
            float gp = sg[8 + jj]  + __ldg(&bihb[8 + jj])  + __ldg(&bhhb[8 + jj]);
            float op = sg[12 + jj] + __ldg(&bihb[12 + jj]) + __ldg(&bhhb[12 + jj]);
            float iv = sigmoidf_(ip);
            float gv = tanhf_(gp);
            float ov = sigmoidf_(op);
            float cc = iv * gv;                 // c0 = 0, so f-gate drops out
            hb[jj] = ov * tanhf_(cc);
            hf[jj] = g_hf[b * HID + jj];
        }
#pragma unroll
        for (int o2 = 0; o2 < 2; ++o2) {
            float s = __ldg(&bout[o2]);
#pragma unroll
            for (int jj = 0; jj < 4; ++jj) {
                s = fmaf(__ldg(&Wout[o2 * 8 + jj]),     hf[jj], s);
                s = fmaf(__ldg(&Wout[o2 * 8 + 4 + jj]), hb[jj], s);
            }
            out[b * 2 + o2] = s;
        }
    }
}

// =====================================================================
extern "C" void kernel_launch(void* const* d_in, const int* in_sizes, int n_in,
                              void* d_out, int out_size) {
    const float* x    = (const float*)d_in[0];
    const float* Wihf = (const float*)d_in[1];
    const float* Whhf = (const float*)d_in[2];
    const float* bihf = (const float*)d_in[3];
    const float* bhhf = (const float*)d_in[4];
    const float* Wihb = (const float*)d_in[5];
    // d_in[6] = W_hh_b: provably unused (backward needs only its first step from zero state)
    const float* bihb = (const float*)d_in[7];
    const float* bhhb = (const float*)d_in[8];
    const float* Wout = (const float*)d_in[9];
    const float* bout = (const float*)d_in[10];
    float* out = (float*)d_out;

    proj_kernel<<<(BATCH * TSEQ) / 128, 128>>>(x, Wihf, bihf, bhhf);
    lstm_fwd_kernel<<<BATCH / 8, 32>>>(Whhf);
    tail_kernel<<<BATCH, 128>>>(x, Wihb, bihb, bhhb, Wout, bout, out);
}